// round 1
// baseline (speedup 1.0000x reference)
#include <cuda_runtime.h>

#define NMAX 100000
#define D 128

// Scratch for X0 = notes @ w  (51.2 MB, fits in GB300 L2)
__device__ float g_X0[(size_t)NMAX * D];

// ---------------------------------------------------------------------------
// GEMM: X0[r] = notes[r] @ w ; also writes rows >= garment into the output
// tail (concat part), saving a separate pass.
// Block: 256 threads, tile = 64 rows x 128 cols. Each thread: 8 rows x 4 cols.
// smem: w (64KB) + notes tile (32KB) = 96KB dynamic.
// ---------------------------------------------------------------------------
__global__ void gemm_kernel(const float* __restrict__ notes,
                            const float* __restrict__ w,
                            float* __restrict__ out,
                            int N, int garment) {
    extern __shared__ float smem[];
    float*  s_w  = smem;               // [128][128]
    float*  s_n  = smem + D * D;       // [64][128]
    float4* s_w4 = (float4*)s_w;
    float4* s_n4 = (float4*)s_n;

    const int t   = threadIdx.x;       // 0..255
    const int tx  = t & 31;            // column group (4 cols each)
    const int ty  = t >> 5;            // row group (8 rows each)
    const int row0 = blockIdx.x * 64;

    // Stage w: 128x128 floats = 4096 float4
    const float4* w4 = (const float4*)w;
    #pragma unroll
    for (int i = t; i < D * D / 4; i += 256) s_w4[i] = w4[i];

    // Stage notes tile: 64x128 floats = 2048 float4 (zero-fill OOB rows)
    const float4* n4 = (const float4*)notes;
    #pragma unroll
    for (int i = t; i < 64 * D / 4; i += 256) {
        int r  = i >> 5;       // row in tile
        int c4 = i & 31;       // float4 col
        int gr = row0 + r;
        float4 v = make_float4(0.f, 0.f, 0.f, 0.f);
        if (gr < N) v = n4[(size_t)gr * (D / 4) + c4];
        s_n4[i] = v;
    }
    __syncthreads();

    float4 acc[8];
    #pragma unroll
    for (int r = 0; r < 8; r++) acc[r] = make_float4(0.f, 0.f, 0.f, 0.f);

    #pragma unroll 4
    for (int k = 0; k < D; k++) {
        float4 wv = s_w4[k * 32 + tx];          // 4 cols of w row k
        #pragma unroll
        for (int r = 0; r < 8; r++) {
            float nv = s_n[(ty * 8 + r) * D + k];  // broadcast within warp
            acc[r].x += nv * wv.x;
            acc[r].y += nv * wv.y;
            acc[r].z += nv * wv.z;
            acc[r].w += nv * wv.w;
        }
    }

    #pragma unroll
    for (int r = 0; r < 8; r++) {
        int gr = row0 + ty * 8 + r;
        if (gr < N) {
            ((float4*)(g_X0 + (size_t)gr * D))[tx] = acc[r];
            if (gr >= garment) {
                // concat tail: out row = N + (gr - garment)
                ((float4*)(out + (size_t)(N + gr - garment) * D))[tx] = acc[r];
            }
        }
    }
}

// ---------------------------------------------------------------------------
// Edge scatter: out[src] += edge_w * X0[dst]   (one warp per edge,
// each lane owns 4 floats; vector float4 RED -> 1 atomic per lane)
// ---------------------------------------------------------------------------
__global__ void edge_kernel(const int* __restrict__ src,
                            const int* __restrict__ dst,
                            const float* __restrict__ ew,
                            float* __restrict__ out, int E) {
    int e    = (int)((blockIdx.x * (size_t)blockDim.x + threadIdx.x) >> 5);
    int lane = threadIdx.x & 31;
    if (e >= E) return;

    int   s   = __ldg(src + e);
    int   d   = __ldg(dst + e);
    float wgt = __ldg(ew + e);

    float4 v = *((const float4*)(g_X0 + (size_t)d * D) + lane);
    v.x *= wgt; v.y *= wgt; v.z *= wgt; v.w *= wgt;

    atomicAdd((float4*)(out + (size_t)s * D) + lane, v);  // RED.v4.f32 on sm_90+
}

// ---------------------------------------------------------------------------
// Finalize: out[i] = max(out[i] + b[col], 0) for the first N rows
// ---------------------------------------------------------------------------
__global__ void relu_bias_kernel(float* __restrict__ out,
                                 const float* __restrict__ b,
                                 size_t n4) {
    size_t i = blockIdx.x * (size_t)blockDim.x + threadIdx.x;
    if (i >= n4) return;
    float4 v  = ((float4*)out)[i];
    float4 bv = ((const float4*)b)[i & 31];   // D/4 = 32 float4 per row
    v.x = fmaxf(v.x + bv.x, 0.f);
    v.y = fmaxf(v.y + bv.y, 0.f);
    v.z = fmaxf(v.z + bv.z, 0.f);
    v.w = fmaxf(v.w + bv.w, 0.f);
    ((float4*)out)[i] = v;
}

extern "C" void kernel_launch(void* const* d_in, const int* in_sizes, int n_in,
                              void* d_out, int out_size) {
    const float* notes = (const float*)d_in[0];
    const float* w     = (const float*)d_in[1];
    const float* b     = (const float*)d_in[2];
    const int*   esrc  = (const int*)d_in[3];
    const int*   edst  = (const int*)d_in[4];
    const float* ew    = (const float*)d_in[5];
    float*       out   = (float*)d_out;

    const int N = in_sizes[0] / D;          // 100000
    const int E = in_sizes[3];              // 1600000
    const int out_rows = out_size / D;      // 120000
    const int garment  = 2 * N - out_rows;  // 80000

    // Zero the accumulation region (first N rows of out)
    cudaMemsetAsync(out, 0, (size_t)N * D * sizeof(float), 0);

    // GEMM: X0 into scratch + concat tail into out
    const int smem_bytes = (D * D + 64 * D) * (int)sizeof(float);  // 96 KB
    cudaFuncSetAttribute(gemm_kernel,
                         cudaFuncAttributeMaxDynamicSharedMemorySize, smem_bytes);
    gemm_kernel<<<(N + 63) / 64, 256, smem_bytes>>>(notes, w, out, N, garment);

    // Edge scatter: 1 warp per edge
    {
        size_t total_threads = (size_t)E * 32;
        int blocks = (int)((total_threads + 255) / 256);
        edge_kernel<<<blocks, 256>>>(esrc, edst, ew, out, E);
    }

    // Bias + ReLU over the first N rows
    {
        size_t n4 = (size_t)N * D / 4;
        int blocks = (int)((n4 + 255) / 256);
        relu_bias_kernel<<<blocks, 256>>>(out, b, n4);
    }
}

// round 2
// speedup vs baseline: 1.5793x; 1.5793x over previous
#include <cuda_runtime.h>

#define D      128
#define NMAX   100000
#define NP     (NMAX + 1)
#define EMAX   1600000
#define SCAN_B 1024
#define NBLK   ((NP + SCAN_B - 1) / SCAN_B)   // 98

// Scratch (device globals — no allocations allowed)
__device__ float g_X0[(size_t)NMAX * D];   // notes @ w  (51.2 MB, L2-resident)
__device__ int   g_deg[NP];
__device__ int   g_offs[NP];
__device__ int   g_bsums[128];
__device__ int   g_cursor[NP];
__device__ int   g_csr_dst[EMAX];
__device__ float g_csr_w[EMAX];

// ---------------------------------------------------------------------------
// GEMM: X0[r] = notes[r] @ w ; rows >= garment also go straight to the
// output concat tail. (fp32 FFMA roofline ~91us; tensor-core port later.)
// ---------------------------------------------------------------------------
__global__ void gemm_kernel(const float* __restrict__ notes,
                            const float* __restrict__ w,
                            float* __restrict__ out,
                            int N, int garment) {
    extern __shared__ float smem[];
    float*  s_w  = smem;               // [128][128]
    float*  s_n  = smem + D * D;       // [64][128]
    float4* s_w4 = (float4*)s_w;
    float4* s_n4 = (float4*)s_n;

    const int t    = threadIdx.x;      // 0..255
    const int tx   = t & 31;           // 4-col group
    const int ty   = t >> 5;           // 8-row group
    const int row0 = blockIdx.x * 64;

    const float4* w4 = (const float4*)w;
    #pragma unroll
    for (int i = t; i < D * D / 4; i += 256) s_w4[i] = w4[i];

    const float4* n4 = (const float4*)notes;
    #pragma unroll
    for (int i = t; i < 64 * D / 4; i += 256) {
        int r  = i >> 5;
        int c4 = i & 31;
        int gr = row0 + r;
        float4 v = make_float4(0.f, 0.f, 0.f, 0.f);
        if (gr < N) v = n4[(size_t)gr * (D / 4) + c4];
        s_n4[i] = v;
    }
    __syncthreads();

    float4 acc[8];
    #pragma unroll
    for (int r = 0; r < 8; r++) acc[r] = make_float4(0.f, 0.f, 0.f, 0.f);

    #pragma unroll 4
    for (int k = 0; k < D; k++) {
        float4 wv = s_w4[k * 32 + tx];
        #pragma unroll
        for (int r = 0; r < 8; r++) {
            float nv = s_n[(ty * 8 + r) * D + k];
            acc[r].x += nv * wv.x;
            acc[r].y += nv * wv.y;
            acc[r].z += nv * wv.z;
            acc[r].w += nv * wv.w;
        }
    }

    #pragma unroll
    for (int r = 0; r < 8; r++) {
        int gr = row0 + ty * 8 + r;
        if (gr < N) {
            ((float4*)(g_X0 + (size_t)gr * D))[tx] = acc[r];
            if (gr >= garment)
                ((float4*)(out + (size_t)(N + gr - garment) * D))[tx] = acc[r];
        }
    }
}

// ---------------------------------------------------------------------------
// CSR build: zero -> degree count -> exclusive scan -> fill
// ---------------------------------------------------------------------------
__global__ void zero_kernel() {
    int i = blockIdx.x * blockDim.x + threadIdx.x;
    if (i < NP) { g_deg[i] = 0; g_cursor[i] = 0; }
}

__global__ void count_kernel(const int* __restrict__ src, int E) {
    int e = blockIdx.x * blockDim.x + threadIdx.x;
    if (e < E) atomicAdd(&g_deg[src[e]], 1);
}

__global__ void scan1_kernel() {           // per-block exclusive scan + block sums
    __shared__ int s[SCAN_B];
    int t = threadIdx.x;
    int i = blockIdx.x * SCAN_B + t;
    int v = (i < NP) ? g_deg[i] : 0;
    s[t] = v; __syncthreads();
    #pragma unroll
    for (int off = 1; off < SCAN_B; off <<= 1) {
        int x = (t >= off) ? s[t - off] : 0;
        __syncthreads();
        s[t] += x; __syncthreads();
    }
    if (i < NP) g_offs[i] = s[t] - v;      // exclusive within block
    if (t == SCAN_B - 1) g_bsums[blockIdx.x] = s[t];
}

__global__ void scan2_kernel() {           // exclusive scan of <=128 block sums
    __shared__ int s[128];
    int t = threadIdx.x;
    int v = (t < NBLK) ? g_bsums[t] : 0;
    s[t] = v; __syncthreads();
    #pragma unroll
    for (int off = 1; off < 128; off <<= 1) {
        int x = (t >= off) ? s[t - off] : 0;
        __syncthreads();
        s[t] += x; __syncthreads();
    }
    if (t < NBLK) g_bsums[t] = s[t] - v;
}

__global__ void scan3_kernel() {           // add block bases
    int i = blockIdx.x * blockDim.x + threadIdx.x;
    if (i < NP) g_offs[i] += g_bsums[i / SCAN_B];
}

__global__ void fill_kernel(const int* __restrict__ src,
                            const int* __restrict__ dst,
                            const float* __restrict__ ew, int E) {
    int e = blockIdx.x * blockDim.x + threadIdx.x;
    if (e >= E) return;
    int s   = src[e];
    int idx = g_offs[s] + atomicAdd(&g_cursor[s], 1);
    g_csr_dst[idx] = dst[e];
    g_csr_w[idx]   = ew[e];
}

// ---------------------------------------------------------------------------
// Node kernel: one warp per node. Gather-only, no atomics, fused bias+ReLU.
// Unrolled x4 for MLP against L2 latency.
// ---------------------------------------------------------------------------
__global__ void node_kernel(const float* __restrict__ b,
                            float* __restrict__ out, int N) {
    int warp = (int)((blockIdx.x * (size_t)blockDim.x + threadIdx.x) >> 5);
    int lane = threadIdx.x & 31;
    if (warp >= N) return;

    int beg = g_offs[warp];
    int end = g_offs[warp + 1];

    float4 acc = make_float4(0.f, 0.f, 0.f, 0.f);
    int i = beg;
    for (; i + 4 <= end; i += 4) {
        int   d0 = g_csr_dst[i],   d1 = g_csr_dst[i+1];
        int   d2 = g_csr_dst[i+2], d3 = g_csr_dst[i+3];
        float w0 = g_csr_w[i],     w1 = g_csr_w[i+1];
        float w2 = g_csr_w[i+2],   w3 = g_csr_w[i+3];
        float4 v0 = ((const float4*)(g_X0 + (size_t)d0 * D))[lane];
        float4 v1 = ((const float4*)(g_X0 + (size_t)d1 * D))[lane];
        float4 v2 = ((const float4*)(g_X0 + (size_t)d2 * D))[lane];
        float4 v3 = ((const float4*)(g_X0 + (size_t)d3 * D))[lane];
        acc.x += w0*v0.x; acc.y += w0*v0.y; acc.z += w0*v0.z; acc.w += w0*v0.w;
        acc.x += w1*v1.x; acc.y += w1*v1.y; acc.z += w1*v1.z; acc.w += w1*v1.w;
        acc.x += w2*v2.x; acc.y += w2*v2.y; acc.z += w2*v2.z; acc.w += w2*v2.w;
        acc.x += w3*v3.x; acc.y += w3*v3.y; acc.z += w3*v3.z; acc.w += w3*v3.w;
    }
    for (; i < end; i++) {
        int   d  = g_csr_dst[i];
        float wg = g_csr_w[i];
        float4 v = ((const float4*)(g_X0 + (size_t)d * D))[lane];
        acc.x += wg*v.x; acc.y += wg*v.y; acc.z += wg*v.z; acc.w += wg*v.w;
    }

    float4 bv = ((const float4*)b)[lane];
    acc.x = fmaxf(acc.x + bv.x, 0.f);
    acc.y = fmaxf(acc.y + bv.y, 0.f);
    acc.z = fmaxf(acc.z + bv.z, 0.f);
    acc.w = fmaxf(acc.w + bv.w, 0.f);
    ((float4*)(out + (size_t)warp * D))[lane] = acc;
}

extern "C" void kernel_launch(void* const* d_in, const int* in_sizes, int n_in,
                              void* d_out, int out_size) {
    const float* notes = (const float*)d_in[0];
    const float* w     = (const float*)d_in[1];
    const float* b     = (const float*)d_in[2];
    const int*   esrc  = (const int*)d_in[3];
    const int*   edst  = (const int*)d_in[4];
    const float* ew    = (const float*)d_in[5];
    float*       out   = (float*)d_out;

    const int N = in_sizes[0] / D;          // 100000
    const int E = in_sizes[3];              // 1600000
    const int out_rows = out_size / D;      // 120000
    const int garment  = 2 * N - out_rows;  // 80000

    // GEMM first (independent of CSR build)
    const int smem_bytes = (D * D + 64 * D) * (int)sizeof(float);  // 96 KB
    cudaFuncSetAttribute(gemm_kernel,
                         cudaFuncAttributeMaxDynamicSharedMemorySize, smem_bytes);
    gemm_kernel<<<(N + 63) / 64, 256, smem_bytes>>>(notes, w, out, N, garment);

    // CSR build
    zero_kernel<<<(NP + 255) / 256, 256>>>();
    count_kernel<<<(E + 255) / 256, 256>>>(esrc, E);
    scan1_kernel<<<NBLK, SCAN_B>>>();
    scan2_kernel<<<1, 128>>>();
    scan3_kernel<<<(NP + 255) / 256, 256>>>();
    fill_kernel<<<(E + 255) / 256, 256>>>(esrc, edst, ew, E);

    // Gather-only aggregation, fused bias + ReLU (8 warps / block)
    node_kernel<<<(N + 7) / 8, 256>>>(b, out, N);
}

// round 3
// speedup vs baseline: 2.0499x; 1.2980x over previous
#include <cuda_runtime.h>

#define D      128
#define NMAX   100000
#define NP     (NMAX + 1)
#define EMAX   1600000
#define SCAN_B 1024
#define NBLK   ((NP + SCAN_B - 1) / SCAN_B)   // 98

// Scratch (device globals — no allocations allowed)
__device__ float    g_X0[(size_t)NMAX * D];   // notes @ w  (51.2 MB)
__device__ unsigned g_wh[64 * D];             // w hi-split, bf16x2 packed along k
__device__ unsigned g_wl[64 * D];             // w lo-split
__device__ int   g_deg[NP];
__device__ int   g_offs[NP];
__device__ int   g_bsums[128];
__device__ int   g_cursor[NP];
__device__ int   g_csr_dst[EMAX];
__device__ float g_csr_w[EMAX];

// ---------------------------------------------------------------------------
// Split w into bf16 hi/lo, packed as {k even -> low16, k odd -> high16} pairs
// for the m16n8k16 B-fragment layout: g_wh[kk][n] covers k = 2kk, 2kk+1.
// ---------------------------------------------------------------------------
__global__ void w_split_kernel(const float* __restrict__ w) {
    int i = blockIdx.x * blockDim.x + threadIdx.x;   // 0 .. 8191
    if (i >= 64 * D) return;
    int kk = i >> 7;          // k pair index
    int n  = i & 127;
    float f0 = w[(2 * kk)     * D + n];
    float f1 = w[(2 * kk + 1) * D + n];
    unsigned h;
    asm("cvt.rn.bf16x2.f32 %0, %1, %2;" : "=r"(h) : "f"(f1), "f"(f0));
    float h0 = __uint_as_float(h << 16);
    float h1 = __uint_as_float(h & 0xffff0000u);
    unsigned l;
    asm("cvt.rn.bf16x2.f32 %0, %1, %2;" : "=r"(l) : "f"(f1 - h1), "f"(f0 - h0));
    g_wh[i] = h;
    g_wl[i] = l;
}

// ---------------------------------------------------------------------------
// Tensor-core GEMM (bf16 3-term compensated): X0 = notes @ w, fp32-accurate
// to ~1e-5. Block = 128 threads (4 warps), 64 rows x 128 cols per block.
// Each warp: 16 rows x 128 cols via mma.sync.m16n8k16.
// Rows >= garment also stream straight into the output concat tail.
// ---------------------------------------------------------------------------
#define SN_PITCH 132
#define SW_PITCH 136

__global__ void __launch_bounds__(128) gemm_mma_kernel(
        const float* __restrict__ notes,
        float* __restrict__ out, int N, int garment) {
    extern __shared__ char smem_raw[];
    float*    s_n  = (float*)smem_raw;                             // [64][132] f32
    unsigned* s_wh = (unsigned*)(smem_raw + 64 * SN_PITCH * 4);    // [64][136] u32
    unsigned* s_wl = s_wh + 64 * SW_PITCH;

    const int t    = threadIdx.x;
    const int warp = t >> 5;
    const int lane = t & 31;
    const int g    = lane >> 2;    // group (row within fragment)
    const int tq   = lane & 3;     // thread-in-group
    const int row0 = blockIdx.x * 64;

    // Stage packed w splits (8192 u32 each -> 2048 uint4 each)
    const uint4* wh4 = (const uint4*)g_wh;
    const uint4* wl4 = (const uint4*)g_wl;
    #pragma unroll
    for (int i = t; i < 2048; i += 128) {
        int kk = i >> 5, c4 = i & 31;
        *(uint4*)&s_wh[kk * SW_PITCH + c4 * 4] = wh4[i];
        *(uint4*)&s_wl[kk * SW_PITCH + c4 * 4] = wl4[i];
    }
    // Stage notes tile (64 x 128 f32), zero-fill OOB rows
    const float4* n4 = (const float4*)notes;
    #pragma unroll
    for (int i = t; i < 2048; i += 128) {
        int r = i >> 5, c4 = i & 31;
        int gr = row0 + r;
        float4 v = make_float4(0.f, 0.f, 0.f, 0.f);
        if (gr < N) v = n4[(size_t)gr * 32 + c4];
        *(float4*)&s_n[r * SN_PITCH + c4 * 4] = v;
    }
    __syncthreads();

    float acc[16][4];
    #pragma unroll
    for (int nt = 0; nt < 16; nt++)
        #pragma unroll
        for (int j = 0; j < 4; j++) acc[nt][j] = 0.f;

    const int arow = warp * 16 + g;

    #pragma unroll
    for (int ks = 0; ks < 8; ks++) {
        // A fragments: split f32 -> bf16 hi/lo on the fly
        unsigned ahi[4], alo[4];
        #pragma unroll
        for (int i = 0; i < 4; i++) {
            int r = arow + (i & 1) * 8;
            int k = ks * 16 + tq * 2 + (i >> 1) * 8;
            float2 f = *(const float2*)&s_n[r * SN_PITCH + k];
            unsigned h;
            asm("cvt.rn.bf16x2.f32 %0, %1, %2;" : "=r"(h) : "f"(f.y), "f"(f.x));
            float hx = __uint_as_float(h << 16);
            float hy = __uint_as_float(h & 0xffff0000u);
            unsigned l;
            asm("cvt.rn.bf16x2.f32 %0, %1, %2;" : "=r"(l) : "f"(f.y - hy), "f"(f.x - hx));
            ahi[i] = h; alo[i] = l;
        }
        #pragma unroll
        for (int nt = 0; nt < 16; nt++) {
            int n = nt * 8 + g;
            unsigned bh0 = s_wh[(ks * 8 + tq)     * SW_PITCH + n];
            unsigned bh1 = s_wh[(ks * 8 + tq + 4) * SW_PITCH + n];
            unsigned bl0 = s_wl[(ks * 8 + tq)     * SW_PITCH + n];
            unsigned bl1 = s_wl[(ks * 8 + tq + 4) * SW_PITCH + n];
            asm volatile(
                "mma.sync.aligned.m16n8k16.row.col.f32.bf16.bf16.f32 "
                "{%0,%1,%2,%3}, {%4,%5,%6,%7}, {%8,%9}, {%0,%1,%2,%3};"
                : "+f"(acc[nt][0]), "+f"(acc[nt][1]), "+f"(acc[nt][2]), "+f"(acc[nt][3])
                : "r"(ahi[0]), "r"(ahi[1]), "r"(ahi[2]), "r"(ahi[3]),
                  "r"(bh0), "r"(bh1));
            asm volatile(
                "mma.sync.aligned.m16n8k16.row.col.f32.bf16.bf16.f32 "
                "{%0,%1,%2,%3}, {%4,%5,%6,%7}, {%8,%9}, {%0,%1,%2,%3};"
                : "+f"(acc[nt][0]), "+f"(acc[nt][1]), "+f"(acc[nt][2]), "+f"(acc[nt][3])
                : "r"(ahi[0]), "r"(ahi[1]), "r"(ahi[2]), "r"(ahi[3]),
                  "r"(bl0), "r"(bl1));
            asm volatile(
                "mma.sync.aligned.m16n8k16.row.col.f32.bf16.bf16.f32 "
                "{%0,%1,%2,%3}, {%4,%5,%6,%7}, {%8,%9}, {%0,%1,%2,%3};"
                : "+f"(acc[nt][0]), "+f"(acc[nt][1]), "+f"(acc[nt][2]), "+f"(acc[nt][3])
                : "r"(alo[0]), "r"(alo[1]), "r"(alo[2]), "r"(alo[3]),
                  "r"(bh0), "r"(bh1));
        }
    }

    // Epilogue: c0,c1 -> row (arow), c2,c3 -> row (arow+8), cols nt*8 + 2tq
    const int r0 = row0 + arow;
    const int r1 = r0 + 8;
    #pragma unroll
    for (int nt = 0; nt < 16; nt++) {
        int col = nt * 8 + tq * 2;
        if (r0 < N) {
            float2 v = make_float2(acc[nt][0], acc[nt][1]);
            *(float2*)&g_X0[(size_t)r0 * D + col] = v;
            if (r0 >= garment)
                *(float2*)&out[(size_t)(N + r0 - garment) * D + col] = v;
        }
        if (r1 < N) {
            float2 v = make_float2(acc[nt][2], acc[nt][3]);
            *(float2*)&g_X0[(size_t)r1 * D + col] = v;
            if (r1 >= garment)
                *(float2*)&out[(size_t)(N + r1 - garment) * D + col] = v;
        }
    }
}

// ---------------------------------------------------------------------------
// CSR build: zero -> degree count -> exclusive scan -> fill
// ---------------------------------------------------------------------------
__global__ void zero_kernel() {
    int i = blockIdx.x * blockDim.x + threadIdx.x;
    if (i < NP) { g_deg[i] = 0; g_cursor[i] = 0; }
}

__global__ void count_kernel(const int* __restrict__ src, int E) {
    int e = blockIdx.x * blockDim.x + threadIdx.x;
    if (e < E) atomicAdd(&g_deg[src[e]], 1);
}

__global__ void scan1_kernel() {
    __shared__ int s[SCAN_B];
    int t = threadIdx.x;
    int i = blockIdx.x * SCAN_B + t;
    int v = (i < NP) ? g_deg[i] : 0;
    s[t] = v; __syncthreads();
    #pragma unroll
    for (int off = 1; off < SCAN_B; off <<= 1) {
        int x = (t >= off) ? s[t - off] : 0;
        __syncthreads();
        s[t] += x; __syncthreads();
    }
    if (i < NP) g_offs[i] = s[t] - v;
    if (t == SCAN_B - 1) g_bsums[blockIdx.x] = s[t];
}

__global__ void scan2_kernel() {
    __shared__ int s[128];
    int t = threadIdx.x;
    int v = (t < NBLK) ? g_bsums[t] : 0;
    s[t] = v; __syncthreads();
    #pragma unroll
    for (int off = 1; off < 128; off <<= 1) {
        int x = (t >= off) ? s[t - off] : 0;
        __syncthreads();
        s[t] += x; __syncthreads();
    }
    if (t < NBLK) g_bsums[t] = s[t] - v;
}

__global__ void scan3_kernel() {
    int i = blockIdx.x * blockDim.x + threadIdx.x;
    if (i < NP) g_offs[i] += g_bsums[i / SCAN_B];
}

__global__ void fill_kernel(const int* __restrict__ src,
                            const int* __restrict__ dst,
                            const float* __restrict__ ew, int E) {
    int e = blockIdx.x * blockDim.x + threadIdx.x;
    if (e >= E) return;
    int s   = src[e];
    int idx = g_offs[s] + atomicAdd(&g_cursor[s], 1);
    g_csr_dst[idx] = dst[e];
    g_csr_w[idx]   = ew[e];
}

// ---------------------------------------------------------------------------
// Node kernel: one warp per node, gather-only, fused bias+ReLU.
// ---------------------------------------------------------------------------
__global__ void node_kernel(const float* __restrict__ b,
                            float* __restrict__ out, int N) {
    int warp = (int)((blockIdx.x * (size_t)blockDim.x + threadIdx.x) >> 5);
    int lane = threadIdx.x & 31;
    if (warp >= N) return;

    int beg = g_offs[warp];
    int end = g_offs[warp + 1];

    float4 acc = make_float4(0.f, 0.f, 0.f, 0.f);
    int i = beg;
    for (; i + 4 <= end; i += 4) {
        int   d0 = g_csr_dst[i],   d1 = g_csr_dst[i+1];
        int   d2 = g_csr_dst[i+2], d3 = g_csr_dst[i+3];
        float w0 = g_csr_w[i],     w1 = g_csr_w[i+1];
        float w2 = g_csr_w[i+2],   w3 = g_csr_w[i+3];
        float4 v0 = ((const float4*)(g_X0 + (size_t)d0 * D))[lane];
        float4 v1 = ((const float4*)(g_X0 + (size_t)d1 * D))[lane];
        float4 v2 = ((const float4*)(g_X0 + (size_t)d2 * D))[lane];
        float4 v3 = ((const float4*)(g_X0 + (size_t)d3 * D))[lane];
        acc.x += w0*v0.x; acc.y += w0*v0.y; acc.z += w0*v0.z; acc.w += w0*v0.w;
        acc.x += w1*v1.x; acc.y += w1*v1.y; acc.z += w1*v1.z; acc.w += w1*v1.w;
        acc.x += w2*v2.x; acc.y += w2*v2.y; acc.z += w2*v2.z; acc.w += w2*v2.w;
        acc.x += w3*v3.x; acc.y += w3*v3.y; acc.z += w3*v3.z; acc.w += w3*v3.w;
    }
    for (; i < end; i++) {
        int   d  = g_csr_dst[i];
        float wg = g_csr_w[i];
        float4 v = ((const float4*)(g_X0 + (size_t)d * D))[lane];
        acc.x += wg*v.x; acc.y += wg*v.y; acc.z += wg*v.z; acc.w += wg*v.w;
    }

    float4 bv = ((const float4*)b)[lane];
    acc.x = fmaxf(acc.x + bv.x, 0.f);
    acc.y = fmaxf(acc.y + bv.y, 0.f);
    acc.z = fmaxf(acc.z + bv.z, 0.f);
    acc.w = fmaxf(acc.w + bv.w, 0.f);
    ((float4*)(out + (size_t)warp * D))[lane] = acc;
}

extern "C" void kernel_launch(void* const* d_in, const int* in_sizes, int n_in,
                              void* d_out, int out_size) {
    const float* notes = (const float*)d_in[0];
    const float* w     = (const float*)d_in[1];
    const float* b     = (const float*)d_in[2];
    const int*   esrc  = (const int*)d_in[3];
    const int*   edst  = (const int*)d_in[4];
    const float* ew    = (const float*)d_in[5];
    float*       out   = (float*)d_out;

    const int N = in_sizes[0] / D;          // 100000
    const int E = in_sizes[3];              // 1600000
    const int out_rows = out_size / D;      // 120000
    const int garment  = 2 * N - out_rows;  // 80000

    // w split (tiny)
    w_split_kernel<<<32, 256>>>(w);

    // Tensor-core GEMM
    const int smem_bytes = (64 * SN_PITCH + 2 * 64 * SW_PITCH) * (int)sizeof(float);
    cudaFuncSetAttribute(gemm_mma_kernel,
                         cudaFuncAttributeMaxDynamicSharedMemorySize, smem_bytes);
    gemm_mma_kernel<<<(N + 63) / 64, 128, smem_bytes>>>(notes, out, N, garment);

    // CSR build
    zero_kernel<<<(NP + 255) / 256, 256>>>();
    count_kernel<<<(E + 255) / 256, 256>>>(esrc, E);
    scan1_kernel<<<NBLK, SCAN_B>>>();
    scan2_kernel<<<1, 128>>>();
    scan3_kernel<<<(NP + 255) / 256, 256>>>();
    fill_kernel<<<(E + 255) / 256, 256>>>(esrc, edst, ew, E);

    // Gather-only aggregation, fused bias + ReLU
    node_kernel<<<(N + 7) / 8, 256>>>(b, out, N);
}

// round 4
// speedup vs baseline: 2.3741x; 1.1582x over previous
#include <cuda_runtime.h>
#include <cuda_fp16.h>

#define D      128
#define NMAX   100000
#define NP     (NMAX + 1)
#define EMAX   1600000
#define SCAN_B 1024
#define NBLK   ((NP + SCAN_B - 1) / SCAN_B)   // 98

#define GEMM_BLOCKS ((NMAX + 63) / 64)        // 1563
#define CNT_BLOCKS  392

// Scratch (device globals — no allocations allowed)
__device__ __half g_X0h[(size_t)NMAX * D];    // notes @ w in fp16 (25.6 MB)
__device__ uint4  g_wfrag[8 * 16 * 32];       // B fragments: {bh0,bh1,bl0,bl1}
__device__ int    g_deg[NP];
__device__ int    g_offs[NP];
__device__ int    g_bsums[128];
__device__ int    g_csr_dst[EMAX];
__device__ float  g_csr_w[EMAX];

static __device__ __forceinline__ unsigned pack_bf16x2(float f0, float f1) {
    unsigned h;
    asm("cvt.rn.bf16x2.f32 %0, %1, %2;" : "=r"(h) : "f"(f1), "f"(f0));
    return h;
}

// ---------------------------------------------------------------------------
// Prep: blocks [0,16) build w fragments in mma register order;
//       blocks [16,..) zero g_deg.
// Fragment f = (ks*16 + nt)*32 + lane; lane: g=lane>>2 (col n=nt*8+g),
// tq=lane&3 (k rows). bh0 covers k = ks*16+2tq,+1 ; bh1 k = ks*16+8+2tq,+1.
// ---------------------------------------------------------------------------
__global__ void prep_kernel(const float* __restrict__ w) {
    if (blockIdx.x < 16) {
        int f = blockIdx.x * 256 + threadIdx.x;   // 0..4095
        int lane = f & 31;
        int nt   = (f >> 5) & 15;
        int ks   = f >> 9;
        int g  = lane >> 2;
        int tq = lane & 3;
        int n  = nt * 8 + g;
        int k0 = ks * 16 + 2 * tq;       // bh0 pair
        int k1 = k0 + 8;                 // bh1 pair

        float a0 = w[(k0)     * D + n];
        float a1 = w[(k0 + 1) * D + n];
        float c0 = w[(k1)     * D + n];
        float c1 = w[(k1 + 1) * D + n];

        unsigned bh0 = pack_bf16x2(a0, a1);
        unsigned bh1 = pack_bf16x2(c0, c1);
        float h0 = __uint_as_float(bh0 << 16);
        float h1 = __uint_as_float(bh0 & 0xffff0000u);
        float h2 = __uint_as_float(bh1 << 16);
        float h3 = __uint_as_float(bh1 & 0xffff0000u);
        unsigned bl0 = pack_bf16x2(a0 - h0, a1 - h1);
        unsigned bl1 = pack_bf16x2(c0 - h2, c1 - h3);

        g_wfrag[f] = make_uint4(bh0, bh1, bl0, bl1);
    } else {
        int z = (blockIdx.x - 16) * 256 + threadIdx.x;
        if (z < NP) g_deg[z] = 0;
    }
}

// ---------------------------------------------------------------------------
// Fused tensor-core GEMM + edge degree count.
// GEMM blocks [0, GEMM_BLOCKS): 64 rows x 128 cols, 4 warps.
// Count blocks [GEMM_BLOCKS, +CNT_BLOCKS): int4 grid-stride degree histogram
// (overlaps L2-atomic work with tensor work).
// ---------------------------------------------------------------------------
#define SN_PITCH 132

__global__ void __launch_bounds__(128) gemm_count_kernel(
        const float* __restrict__ notes,
        const int*   __restrict__ esrc,
        float* __restrict__ out, int N, int garment, int E) {
    if (blockIdx.x >= GEMM_BLOCKS) {
        // ---- degree count path ----
        int cb   = blockIdx.x - GEMM_BLOCKS;
        int tidg = cb * 128 + threadIdx.x;
        int nth  = CNT_BLOCKS * 128;
        int E4   = E >> 2;
        const int4* s4 = (const int4*)esrc;
        for (int i = tidg; i < E4; i += nth) {
            int4 s = s4[i];
            atomicAdd(&g_deg[s.x], 1);
            atomicAdd(&g_deg[s.y], 1);
            atomicAdd(&g_deg[s.z], 1);
            atomicAdd(&g_deg[s.w], 1);
        }
        if (tidg == 0)
            for (int e = E4 << 2; e < E; e++) atomicAdd(&g_deg[esrc[e]], 1);
        return;
    }

    extern __shared__ char smem_raw[];
    float* s_n  = (float*)smem_raw;                           // [64][132] f32
    uint4* s_bf = (uint4*)(smem_raw + 64 * SN_PITCH * 4);     // [8*16*32]

    const int t    = threadIdx.x;
    const int warp = t >> 5;
    const int lane = t & 31;
    const int g    = lane >> 2;
    const int tq   = lane & 3;
    const int row0 = blockIdx.x * 64;

    // Stage B fragments (4096 uint4)
    #pragma unroll
    for (int i = t; i < 4096; i += 128) s_bf[i] = g_wfrag[i];

    // Stage notes tile (64 x 128 f32), zero-fill OOB rows
    const float4* n4 = (const float4*)notes;
    #pragma unroll
    for (int i = t; i < 2048; i += 128) {
        int r = i >> 5, c4 = i & 31;
        int gr = row0 + r;
        float4 v = make_float4(0.f, 0.f, 0.f, 0.f);
        if (gr < N) v = n4[(size_t)gr * 32 + c4];
        *(float4*)&s_n[r * SN_PITCH + c4 * 4] = v;
    }
    __syncthreads();

    float acc[16][4];
    #pragma unroll
    for (int nt = 0; nt < 16; nt++)
        #pragma unroll
        for (int j = 0; j < 4; j++) acc[nt][j] = 0.f;

    const int arow = warp * 16 + g;

    #pragma unroll
    for (int ks = 0; ks < 8; ks++) {
        // A fragments: f32 -> bf16 hi/lo split on the fly
        unsigned ahi[4], alo[4];
        #pragma unroll
        for (int i = 0; i < 4; i++) {
            int r = arow + (i & 1) * 8;
            int k = ks * 16 + tq * 2 + (i >> 1) * 8;
            float2 f = *(const float2*)&s_n[r * SN_PITCH + k];
            unsigned h = pack_bf16x2(f.x, f.y);
            float hx = __uint_as_float(h << 16);
            float hy = __uint_as_float(h & 0xffff0000u);
            ahi[i] = h;
            alo[i] = pack_bf16x2(f.x - hx, f.y - hy);
        }
        const uint4* bf = &s_bf[ks * 16 * 32 + lane];
        #pragma unroll
        for (int nt = 0; nt < 16; nt++) {
            uint4 f = bf[nt * 32];
            asm volatile(
                "mma.sync.aligned.m16n8k16.row.col.f32.bf16.bf16.f32 "
                "{%0,%1,%2,%3}, {%4,%5,%6,%7}, {%8,%9}, {%0,%1,%2,%3};"
                : "+f"(acc[nt][0]), "+f"(acc[nt][1]), "+f"(acc[nt][2]), "+f"(acc[nt][3])
                : "r"(ahi[0]), "r"(ahi[1]), "r"(ahi[2]), "r"(ahi[3]),
                  "r"(f.x), "r"(f.y));
            asm volatile(
                "mma.sync.aligned.m16n8k16.row.col.f32.bf16.bf16.f32 "
                "{%0,%1,%2,%3}, {%4,%5,%6,%7}, {%8,%9}, {%0,%1,%2,%3};"
                : "+f"(acc[nt][0]), "+f"(acc[nt][1]), "+f"(acc[nt][2]), "+f"(acc[nt][3])
                : "r"(ahi[0]), "r"(ahi[1]), "r"(ahi[2]), "r"(ahi[3]),
                  "r"(f.z), "r"(f.w));
            asm volatile(
                "mma.sync.aligned.m16n8k16.row.col.f32.bf16.bf16.f32 "
                "{%0,%1,%2,%3}, {%4,%5,%6,%7}, {%8,%9}, {%0,%1,%2,%3};"
                : "+f"(acc[nt][0]), "+f"(acc[nt][1]), "+f"(acc[nt][2]), "+f"(acc[nt][3])
                : "r"(alo[0]), "r"(alo[1]), "r"(alo[2]), "r"(alo[3]),
                  "r"(f.x), "r"(f.y));
        }
    }

    // Epilogue: X0 -> fp16 scratch; rows >= garment -> fp32 output tail.
    const int r0 = row0 + arow;
    const int r1 = r0 + 8;
    #pragma unroll
    for (int nt = 0; nt < 16; nt++) {
        int col = nt * 8 + tq * 2;
        if (r0 < N) {
            *(half2*)&g_X0h[(size_t)r0 * D + col] = __floats2half2_rn(acc[nt][0], acc[nt][1]);
            if (r0 >= garment)
                *(float2*)&out[(size_t)(N + r0 - garment) * D + col] =
                    make_float2(acc[nt][0], acc[nt][1]);
        }
        if (r1 < N) {
            *(half2*)&g_X0h[(size_t)r1 * D + col] = __floats2half2_rn(acc[nt][2], acc[nt][3]);
            if (r1 >= garment)
                *(float2*)&out[(size_t)(N + r1 - garment) * D + col] =
                    make_float2(acc[nt][2], acc[nt][3]);
        }
    }
}

// ---------------------------------------------------------------------------
// Scans: shuffle-based per-block scan + block-sum fixup
// ---------------------------------------------------------------------------
__global__ void scan1_kernel() {
    __shared__ int wsum[32];
    int t = threadIdx.x;
    int lane = t & 31, warp = t >> 5;
    int i = blockIdx.x * SCAN_B + t;
    int v = (i < NP) ? g_deg[i] : 0;

    int x = v;
    #pragma unroll
    for (int off = 1; off < 32; off <<= 1) {
        int y = __shfl_up_sync(0xffffffffu, x, off);
        if (lane >= off) x += y;
    }
    if (lane == 31) wsum[warp] = x;
    __syncthreads();
    if (warp == 0) {
        int s = wsum[lane];
        #pragma unroll
        for (int off = 1; off < 32; off <<= 1) {
            int y = __shfl_up_sync(0xffffffffu, s, off);
            if (lane >= off) s += y;
        }
        wsum[lane] = s;
    }
    __syncthreads();
    int incl = x + ((warp > 0) ? wsum[warp - 1] : 0);
    if (i < NP) g_offs[i] = incl - v;
    if (t == SCAN_B - 1) g_bsums[blockIdx.x] = incl;
}

__global__ void scan2_kernel() {
    __shared__ int s[128];
    int t = threadIdx.x;
    int v = (t < NBLK) ? g_bsums[t] : 0;
    s[t] = v; __syncthreads();
    #pragma unroll
    for (int off = 1; off < 128; off <<= 1) {
        int x = (t >= off) ? s[t - off] : 0;
        __syncthreads();
        s[t] += x; __syncthreads();
    }
    if (t < NBLK) g_bsums[t] = s[t] - v;
}

__global__ void scan3_kernel() {
    int i = blockIdx.x * blockDim.x + threadIdx.x;
    if (i < NP) g_offs[i] += g_bsums[i / SCAN_B];
}

// ---------------------------------------------------------------------------
// Fill: single atomic per edge directly on g_offs (offs ends up shifted by
// one segment; node kernel compensates).
// ---------------------------------------------------------------------------
__global__ void fill_kernel(const int* __restrict__ src,
                            const int* __restrict__ dst,
                            const float* __restrict__ ew, int E) {
    int i4 = blockIdx.x * blockDim.x + threadIdx.x;
    int E4 = E >> 2;
    if (i4 < E4) {
        int4   s = ((const int4*)src)[i4];
        int4   d = ((const int4*)dst)[i4];
        float4 w = ((const float4*)ew)[i4];
        int idx;
        idx = atomicAdd(&g_offs[s.x], 1); g_csr_dst[idx] = d.x; g_csr_w[idx] = w.x;
        idx = atomicAdd(&g_offs[s.y], 1); g_csr_dst[idx] = d.y; g_csr_w[idx] = w.y;
        idx = atomicAdd(&g_offs[s.z], 1); g_csr_dst[idx] = d.z; g_csr_w[idx] = w.z;
        idx = atomicAdd(&g_offs[s.w], 1); g_csr_dst[idx] = d.w; g_csr_w[idx] = w.w;
    }
    if (i4 == 0) {
        for (int e = E4 << 2; e < E; e++) {
            int idx = atomicAdd(&g_offs[src[e]], 1);
            g_csr_dst[idx] = dst[e];
            g_csr_w[idx]   = ew[e];
        }
    }
}

// ---------------------------------------------------------------------------
// Node kernel: one warp per node, fp16 gather (half traffic), fp32 accumulate,
// fused bias+ReLU. After fill, offs[i] = end of segment i.
// ---------------------------------------------------------------------------
__global__ void node_kernel(const float* __restrict__ b,
                            float* __restrict__ out, int N) {
    int node = (int)((blockIdx.x * (size_t)blockDim.x + threadIdx.x) >> 5);
    int lane = threadIdx.x & 31;
    if (node >= N) return;

    int beg = (node == 0) ? 0 : g_offs[node - 1];
    int end = g_offs[node];

    float4 acc = make_float4(0.f, 0.f, 0.f, 0.f);
    int i = beg;
    for (; i + 4 <= end; i += 4) {
        int   d0 = g_csr_dst[i],   d1 = g_csr_dst[i+1];
        int   d2 = g_csr_dst[i+2], d3 = g_csr_dst[i+3];
        float w0 = g_csr_w[i],     w1 = g_csr_w[i+1];
        float w2 = g_csr_w[i+2],   w3 = g_csr_w[i+3];
        uint2 u0 = ((const uint2*)(g_X0h + (size_t)d0 * D))[lane];
        uint2 u1 = ((const uint2*)(g_X0h + (size_t)d1 * D))[lane];
        uint2 u2 = ((const uint2*)(g_X0h + (size_t)d2 * D))[lane];
        uint2 u3 = ((const uint2*)(g_X0h + (size_t)d3 * D))[lane];
        float2 a, c;
        a = __half22float2(*(half2*)&u0.x); c = __half22float2(*(half2*)&u0.y);
        acc.x += w0*a.x; acc.y += w0*a.y; acc.z += w0*c.x; acc.w += w0*c.y;
        a = __half22float2(*(half2*)&u1.x); c = __half22float2(*(half2*)&u1.y);
        acc.x += w1*a.x; acc.y += w1*a.y; acc.z += w1*c.x; acc.w += w1*c.y;
        a = __half22float2(*(half2*)&u2.x); c = __half22float2(*(half2*)&u2.y);
        acc.x += w2*a.x; acc.y += w2*a.y; acc.z += w2*c.x; acc.w += w2*c.y;
        a = __half22float2(*(half2*)&u3.x); c = __half22float2(*(half2*)&u3.y);
        acc.x += w3*a.x; acc.y += w3*a.y; acc.z += w3*c.x; acc.w += w3*c.y;
    }
    for (; i < end; i++) {
        int   d  = g_csr_dst[i];
        float wg = g_csr_w[i];
        uint2 u = ((const uint2*)(g_X0h + (size_t)d * D))[lane];
        float2 a = __half22float2(*(half2*)&u.x);
        float2 c = __half22float2(*(half2*)&u.y);
        acc.x += wg*a.x; acc.y += wg*a.y; acc.z += wg*c.x; acc.w += wg*c.y;
    }

    float4 bv = ((const float4*)b)[lane];
    acc.x = fmaxf(acc.x + bv.x, 0.f);
    acc.y = fmaxf(acc.y + bv.y, 0.f);
    acc.z = fmaxf(acc.z + bv.z, 0.f);
    acc.w = fmaxf(acc.w + bv.w, 0.f);
    ((float4*)(out + (size_t)node * D))[lane] = acc;
}

extern "C" void kernel_launch(void* const* d_in, const int* in_sizes, int n_in,
                              void* d_out, int out_size) {
    const float* notes = (const float*)d_in[0];
    const float* w     = (const float*)d_in[1];
    const float* b     = (const float*)d_in[2];
    const int*   esrc  = (const int*)d_in[3];
    const int*   edst  = (const int*)d_in[4];
    const float* ew    = (const float*)d_in[5];
    float*       out   = (float*)d_out;

    const int N = in_sizes[0] / D;          // 100000
    const int E = in_sizes[3];              // 1600000
    const int out_rows = out_size / D;      // 120000
    const int garment  = 2 * N - out_rows;  // 80000

    // w fragments + zero degrees
    prep_kernel<<<16 + (NP + 255) / 256, 256>>>(w);

    // Fused tensor-core GEMM + degree count
    const int smem_bytes = 64 * SN_PITCH * 4 + 4096 * 16;   // 99,328 B
    cudaFuncSetAttribute(gemm_count_kernel,
                         cudaFuncAttributeMaxDynamicSharedMemorySize, smem_bytes);
    gemm_count_kernel<<<GEMM_BLOCKS + CNT_BLOCKS, 128, smem_bytes>>>(
        notes, esrc, out, N, garment, E);

    // Offsets
    scan1_kernel<<<NBLK, SCAN_B>>>();
    scan2_kernel<<<1, 128>>>();
    scan3_kernel<<<(NP + 255) / 256, 256>>>();

    // CSR fill (single atomic per edge)
    fill_kernel<<<((E >> 2) + 255) / 256, 256>>>(esrc, edst, ew, E);

    // Gather-only aggregation, fp16 messages, fused bias + ReLU
    node_kernel<<<(N + 7) / 8, 256>>>(b, out, N);
}